// round 14
// baseline (speedup 1.0000x reference)
#include <cuda_runtime.h>

#define B 8
#define S 64
#define V 50257
#define P 200
#define NCHUNK 4
#define GRID (S * 2 * NCHUNK)    // 512 CTAs; single resident wave at 4 CTAs/SM
#define THREADS 256
#define MWORDS 400               // max chunk span ~12564 floats -> 393 words
#define INV_T  (1.0f/0.6f)
#define PEN    1.2f
#define INV_PEN (1.0f/1.2f)
#define BSTRIDE  ((size_t)S * V)

__device__ float g_pl[S * NCHUNK * B];     // phase-1 partial sums
__device__ unsigned g_arrive;              // monotonic barrier ticket (never reset)

// Aligned vector range for (s, chunk c): v = a + 4g is 16B-aligned for every
// batch row (since (b*S+s)*V ≡ s mod 4 and BSTRIDE % 4 == 0).
__device__ __forceinline__ void chunk_range(int s, int c, int& a, int& G, int& v0, int& v1) {
    a = (4 - (s & 3)) & 3;
    G = (V - a) >> 2;
    const int g0 = (int)(((long long)c * G) / NCHUNK);
    const int g1 = (int)(((long long)(c + 1) * G) / NCHUNK);
    v0 = a + 4 * g0;
    v1 = a + 4 * g1;
}

// all_neg over all 8 batch rows at position v (rare path; ~0.4% of elements).
__device__ __forceinline__ float penal_fac(const float* __restrict__ logits,
                                           int s, int v) {
    bool allneg = true;
#pragma unroll
    for (int b = 0; b < B; b++)
        allneg = allneg && (logits[((size_t)b * S + s) * V + v] < 0.0f);
    return (allneg ? PEN : INV_PEN) * INV_T;
}

__global__ __launch_bounds__(THREADS, 4) void k_fused(const float* __restrict__ logits,
                                                      const int* __restrict__ prev,
                                                      float* __restrict__ out) {
    const int c = blockIdx.x % NCHUNK;
    const int t = blockIdx.x / NCHUNK;
    const int b0 = (t & 1) * 4;
    const int s = t >> 1;
    int a, G, v0, v1;
    chunk_range(s, c, a, G, v0, v1);

    __shared__ unsigned smask[MWORDS];
    __shared__ int sprev[P];
    __shared__ float ssum[THREADS / 32][4];
    __shared__ float sR[4];

    // ---- mask build ----
    for (int i = threadIdx.x; i < MWORDS; i += THREADS) smask[i] = 0u;
    __syncthreads();
    for (int p = threadIdx.x; p < P; p += THREADS) {
        const int tok = prev[s * P + p];
        sprev[p] = tok;
        if (tok >= v0 && tok < v1) {
            const int r = tok - v0;
            atomicOr(&smask[r >> 5], 1u << (r & 31));
        }
    }
    __syncthreads();

    const float* base[4];
    float* obase[4];
#pragma unroll
    for (int i = 0; i < 4; i++) {
        base[i] = logits + ((size_t)(b0 + i) * S + s) * V;
        obase[i] = out + ((size_t)(b0 + i) * S + s) * V;
    }

    // ==== phase 1: e = exp(penalized/T) -> out (dirty, L2-hot) + row sums ====
    float sum[4] = {0.0f, 0.0f, 0.0f, 0.0f};
    for (int v = v0 + 4 * (int)threadIdx.x; v < v1; v += 4 * THREADS) {
        const int r = v - v0;
        const unsigned bits4 = (smask[r >> 5] >> (r & 31)) & 0xFu;
        float4 x[4];
#pragma unroll
        for (int i = 0; i < 4; i++) x[i] = __ldcs((const float4*)(base[i] + v));
        float fac0 = INV_T, fac1 = INV_T, fac2 = INV_T, fac3 = INV_T;
        if (bits4 != 0u) {                        // rare (~0.4% of groups)
            if (bits4 & 1u) fac0 = penal_fac(logits, s, v + 0);
            if (bits4 & 2u) fac1 = penal_fac(logits, s, v + 1);
            if (bits4 & 4u) fac2 = penal_fac(logits, s, v + 2);
            if (bits4 & 8u) fac3 = penal_fac(logits, s, v + 3);
        }
#pragma unroll
        for (int i = 0; i < 4; i++) {
            float4 e;
            e.x = __expf(x[i].x * fac0);
            e.y = __expf(x[i].y * fac1);
            e.z = __expf(x[i].z * fac2);
            e.w = __expf(x[i].w * fac3);
            sum[i] += e.x + e.y + e.z + e.w;
            *(float4*)(obase[i] + v) = e;         // default .wb: keep dirty in L2
        }
    }
    if (c == 0) {                                 // unaligned head/tail (<=6)
        const int tail0 = a + 4 * G;
        const int cnt = a + (V - tail0);
        if ((int)threadIdx.x < cnt) {
            const int v = ((int)threadIdx.x < a) ? (int)threadIdx.x
                                                 : tail0 + ((int)threadIdx.x - a);
            bool hit = false;
            for (int p = 0; p < P; p++) hit |= (sprev[p] == v);
            const float fac = hit ? penal_fac(logits, s, v) : INV_T;
#pragma unroll
            for (int i = 0; i < 4; i++) {
                const float e = __expf(base[i][v] * fac);
                sum[i] += e;
                obase[i][v] = e;
            }
        }
    }

#pragma unroll
    for (int i = 0; i < 4; i++) {
#pragma unroll
        for (int off = 16; off; off >>= 1)
            sum[i] += __shfl_xor_sync(0xffffffffu, sum[i], off);
    }
    const int warp = threadIdx.x >> 5;
    if ((threadIdx.x & 31) == 0) {
#pragma unroll
        for (int i = 0; i < 4; i++) ssum[warp][i] = sum[i];
    }
    __syncthreads();
    if (threadIdx.x < 4) {
        const int i = threadIdx.x;
        float L = 0.0f;
#pragma unroll
        for (int w = 0; w < THREADS / 32; w++) L += ssum[w][i];
        g_pl[(s * NCHUNK + c) * B + b0 + i] = L;
    }

    // ==== grid barrier (single resident wave; monotonic ticket) ====
    __threadfence();
    __syncthreads();
    if (threadIdx.x == 0) {
        const unsigned ticket = atomicAdd(&g_arrive, 1u);
        const unsigned target = (ticket / GRID + 1u) * GRID;
        while (*(volatile unsigned*)&g_arrive < target) { __nanosleep(32); }
    }
    __syncthreads();

    // ==== phase 2: in-place scale (reads hit dirty L2; no exp, no mask) ====
    if (threadIdx.x < 4) {
        const int b = b0 + (int)threadIdx.x;
        float L = 0.0f;
#pragma unroll
        for (int cc = 0; cc < NCHUNK; cc++)
            L += __ldcg(&g_pl[(s * NCHUNK + cc) * B + b]);
        sR[threadIdx.x] = 1.0f / L;
    }
    __syncthreads();
    float R[4];
#pragma unroll
    for (int i = 0; i < 4; i++) R[i] = sR[i];

    for (int v = v0 + 4 * (int)threadIdx.x; v < v1; v += 4 * THREADS) {
#pragma unroll
        for (int i = 0; i < 4; i++) {
            float4 o = *(const float4*)(obase[i] + v);   // dirty-L2 hit
            o.x *= R[i]; o.y *= R[i]; o.z *= R[i]; o.w *= R[i];
            __stcs((float4*)(obase[i] + v), o);          // final: stream out
        }
    }
    if (c == 0) {
        const int tail0 = a + 4 * G;
        const int cnt = a + (V - tail0);
        if ((int)threadIdx.x < cnt) {
            const int v = ((int)threadIdx.x < a) ? (int)threadIdx.x
                                                 : tail0 + ((int)threadIdx.x - a);
#pragma unroll
            for (int i = 0; i < 4; i++) obase[i][v] *= R[i];
        }
    }
}

extern "C" void kernel_launch(void* const* d_in, const int* in_sizes, int n_in,
                              void* d_out, int out_size) {
    const float* logits = (const float*)d_in[0];
    const int* prev = (const int*)d_in[1];
    float* out = (float*)d_out;
    (void)in_sizes; (void)n_in; (void)out_size;

    k_fused<<<GRID, THREADS>>>(logits, prev, out);
}

// round 15
// speedup vs baseline: 1.2606x; 1.2606x over previous
#include <cuda_runtime.h>

#define B 8
#define S 64
#define V 50257
#define P 200
#define NCHUNK 9
#define THREADS 256
#define MWORDS 180            // covers max chunk span (<=5592 floats -> 175 words) + pad
#define INV_T  (1.0f/0.6f)
#define PEN    1.2f
#define INV_PEN (1.0f/1.2f)
#define BSTRIDE  ((size_t)S * V)       // 3216448 (divisible by 4)
#define BSTRIDE4 (BSTRIDE / 4)

__device__ float g_pl[S * NCHUNK * B];

// Compute this CTA's aligned vector range for sequence s, chunk c.
__device__ __forceinline__ void chunk_range(int s, int c, int& a, int& G, int& v0, int& v1) {
    a = (4 - (s & 3)) & 3;               // first v with (s*V + v) % 4 == 0
    G = (V - a) >> 2;                    // total float4 groups for this s
    const int g0 = (int)(((long long)c * G) / NCHUNK);
    const int g1 = (int)(((long long)(c + 1) * G) / NCHUNK);
    v0 = a + 4 * g0;
    v1 = a + 4 * g1;
}

__device__ __forceinline__ void build_mask(unsigned* smask, int* sprev,
                                           const int* __restrict__ prev,
                                           int s, int v0, int v1) {
    for (int i = threadIdx.x; i < MWORDS; i += THREADS) smask[i] = 0u;
    __syncthreads();
    for (int t = threadIdx.x; t < P; t += THREADS) {
        const int tok = prev[s * P + t];
        sprev[t] = tok;
        if (tok >= v0 && tok < v1) {
            const int r = tok - v0;
            atomicOr(&smask[r >> 5], 1u << (r & 31));
        }
    }
}

// Pass A: partial sums of exp(penalized * 1/T) per (s, chunk, b).
__global__ __launch_bounds__(THREADS, 4) void k_passA(const float* __restrict__ logits,
                                                      const int* __restrict__ prev) {
    const int c = blockIdx.x % NCHUNK;
    const int s = blockIdx.x / NCHUNK;
    int a, G, v0, v1;
    chunk_range(s, c, a, G, v0, v1);

    __shared__ unsigned smask[MWORDS];
    __shared__ int sprev[P];
    build_mask(smask, sprev, prev, s, v0, v1);
    __syncthreads();

    const float* base = logits + (size_t)s * V;
    float sum[B];
#pragma unroll
    for (int b = 0; b < B; b++) sum[b] = 0.0f;

    for (int v = v0 + 4 * (int)threadIdx.x; v < v1; v += 4 * THREADS) {
        const int r = v - v0;                         // multiple of 4 -> no word straddle
        const unsigned bits4 = (smask[r >> 5] >> (r & 31)) & 0xFu;
        const float4* p = (const float4*)(base + v);
        float4 x[B];
#pragma unroll
        for (int b = 0; b < B; b++) x[b] = p[(size_t)b * BSTRIDE4];
        float4 mx = x[0];
#pragma unroll
        for (int b = 1; b < B; b++) {
            mx.x = fmaxf(mx.x, x[b].x); mx.y = fmaxf(mx.y, x[b].y);
            mx.z = fmaxf(mx.z, x[b].z); mx.w = fmaxf(mx.w, x[b].w);
        }
        float fac[4];
        fac[0] = ((bits4 & 1u) ? (mx.x < 0.0f ? PEN : INV_PEN) : 1.0f) * INV_T;
        fac[1] = ((bits4 & 2u) ? (mx.y < 0.0f ? PEN : INV_PEN) : 1.0f) * INV_T;
        fac[2] = ((bits4 & 4u) ? (mx.z < 0.0f ? PEN : INV_PEN) : 1.0f) * INV_T;
        fac[3] = ((bits4 & 8u) ? (mx.w < 0.0f ? PEN : INV_PEN) : 1.0f) * INV_T;
#pragma unroll
        for (int b = 0; b < B; b++)
            sum[b] += __expf(x[b].x * fac[0]) + __expf(x[b].y * fac[1])
                    + __expf(x[b].z * fac[2]) + __expf(x[b].w * fac[3]);
    }

    // chunk 0 handles the <=6 unaligned scalar elements (head [0,a), tail [a+4G, V))
    if (c == 0) {
        const int tail0 = a + 4 * G;
        const int cnt = a + (V - tail0);
        if ((int)threadIdx.x < cnt) {
            const int v = ((int)threadIdx.x < a) ? (int)threadIdx.x
                                                 : tail0 + ((int)threadIdx.x - a);
            bool hit = false;
            for (int t = 0; t < P; t++) hit |= (sprev[t] == v);
            float x[B];
            bool allneg = true;
#pragma unroll
            for (int b = 0; b < B; b++) {
                x[b] = base[(size_t)b * BSTRIDE + v];
                allneg = allneg && (x[b] < 0.0f);
            }
            const float fac = (hit ? (allneg ? PEN : INV_PEN) : 1.0f) * INV_T;
#pragma unroll
            for (int b = 0; b < B; b++) sum[b] += __expf(x[b] * fac);
        }
    }

    // block reduce
#pragma unroll
    for (int b = 0; b < B; b++) {
#pragma unroll
        for (int off = 16; off; off >>= 1)
            sum[b] += __shfl_xor_sync(0xffffffffu, sum[b], off);
    }
    __shared__ float ssum[THREADS / 32][B];
    const int warp = threadIdx.x >> 5;
    const int lane = threadIdx.x & 31;
    if (lane == 0) {
#pragma unroll
        for (int b = 0; b < B; b++) ssum[warp][b] = sum[b];
    }
    __syncthreads();
    if (threadIdx.x < B) {
        const int b = threadIdx.x;
        float L = 0.0f;
#pragma unroll
        for (int w = 0; w < THREADS / 32; w++) L += ssum[w][b];
        g_pl[(s * NCHUNK + c) * B + b] = L;
    }
}

// Pass C: inline chunk-reduce, recompute penalized exp, normalize, stream out.
__global__ __launch_bounds__(THREADS, 4) void k_passC(const float* __restrict__ logits,
                                                      const int* __restrict__ prev,
                                                      float* __restrict__ out) {
    const int c = blockIdx.x % NCHUNK;
    const int s = blockIdx.x / NCHUNK;
    int a, G, v0, v1;
    chunk_range(s, c, a, G, v0, v1);

    __shared__ unsigned smask[MWORDS];
    __shared__ int sprev[P];
    __shared__ float sR[B];
    build_mask(smask, sprev, prev, s, v0, v1);
    if (threadIdx.x < B) {
        float L = 0.0f;
#pragma unroll
        for (int cc = 0; cc < NCHUNK; cc++)
            L += g_pl[(s * NCHUNK + cc) * B + threadIdx.x];
        sR[threadIdx.x] = 1.0f / L;
    }
    __syncthreads();

    float R[B];
#pragma unroll
    for (int b = 0; b < B; b++) R[b] = sR[b];

    const float* base = logits + (size_t)s * V;
    float* obase = out + (size_t)s * V;

    for (int v = v0 + 4 * (int)threadIdx.x; v < v1; v += 4 * THREADS) {
        const int r = v - v0;
        const unsigned bits4 = (smask[r >> 5] >> (r & 31)) & 0xFu;
        const float4* p = (const float4*)(base + v);
        float4* q = (float4*)(obase + v);
        float4 x[B];
#pragma unroll
        for (int b = 0; b < B; b++) x[b] = p[(size_t)b * BSTRIDE4];   // default: L2 hit
        float4 mx = x[0];
#pragma unroll
        for (int b = 1; b < B; b++) {
            mx.x = fmaxf(mx.x, x[b].x); mx.y = fmaxf(mx.y, x[b].y);
            mx.z = fmaxf(mx.z, x[b].z); mx.w = fmaxf(mx.w, x[b].w);
        }
        float fac[4];
        fac[0] = ((bits4 & 1u) ? (mx.x < 0.0f ? PEN : INV_PEN) : 1.0f) * INV_T;
        fac[1] = ((bits4 & 2u) ? (mx.y < 0.0f ? PEN : INV_PEN) : 1.0f) * INV_T;
        fac[2] = ((bits4 & 4u) ? (mx.z < 0.0f ? PEN : INV_PEN) : 1.0f) * INV_T;
        fac[3] = ((bits4 & 8u) ? (mx.w < 0.0f ? PEN : INV_PEN) : 1.0f) * INV_T;
#pragma unroll
        for (int b = 0; b < B; b++) {
            float4 o;
            o.x = __expf(x[b].x * fac[0]) * R[b];
            o.y = __expf(x[b].y * fac[1]) * R[b];
            o.z = __expf(x[b].z * fac[2]) * R[b];
            o.w = __expf(x[b].w * fac[3]) * R[b];
            __stcs(q + (size_t)b * BSTRIDE4, o);        // evict-first: spare L2 for logits
        }
    }

    if (c == 0) {
        const int tail0 = a + 4 * G;
        const int cnt = a + (V - tail0);
        if ((int)threadIdx.x < cnt) {
            const int v = ((int)threadIdx.x < a) ? (int)threadIdx.x
                                                 : tail0 + ((int)threadIdx.x - a);
            bool hit = false;
            for (int t = 0; t < P; t++) hit |= (sprev[t] == v);
            float x[B];
            bool allneg = true;
#pragma unroll
            for (int b = 0; b < B; b++) {
                x[b] = base[(size_t)b * BSTRIDE + v];
                allneg = allneg && (x[b] < 0.0f);
            }
            const float fac = (hit ? (allneg ? PEN : INV_PEN) : 1.0f) * INV_T;
#pragma unroll
            for (int b = 0; b < B; b++)
                obase[(size_t)b * BSTRIDE + v] = __expf(x[b] * fac) * R[b];
        }
    }
}

extern "C" void kernel_launch(void* const* d_in, const int* in_sizes, int n_in,
                              void* d_out, int out_size) {
    const float* logits = (const float*)d_in[0];
    const int* prev = (const int*)d_in[1];
    float* out = (float*)d_out;
    (void)in_sizes; (void)n_in; (void)out_size;

    k_passA<<<S * NCHUNK, THREADS>>>(logits, prev);
    k_passC<<<S * NCHUNK, THREADS>>>(logits, prev, out);
}